// round 6
// baseline (speedup 1.0000x reference)
#include <cuda_runtime.h>
#include <math.h>
#include <stdint.h>

#define BATCH 4
#define SEQ   1024
#define DM    1024
#define NH    16
#define HD    64
#define BH    (BATCH*NH)

__device__ float g_Qh [BATCH*NH*SEQ*HD];        // [B,H,S,hd]  (tf32-rounded)
__device__ float g_Kh [BATCH*NH*SEQ*HD];        // [B,H,S,hd]  (tf32-rounded)
__device__ float g_VhT[BATCH*NH*HD*SEQ];        // [B,H,hd,S]  (tf32-rounded)
__device__ float g_AO [BATCH*SEQ*DM];           // [B,S,D] attn out (fp32)
__device__ float g_PE [SEQ*HD];                 // sinusoidal PE table

// ---------------------------------------------------------------------------
__global__ void pe_init_kernel() {
    int idx = blockIdx.x * blockDim.x + threadIdx.x;
    if (idx >= SEQ * HD) return;
    int s = idx >> 6;
    int d = idx & 63;
    int de = d & ~1;
    float div = expf(-(float)de * 0.14391156831212787f);   // ln(10000)/64
    float ang = (float)s * div;
    g_PE[idx] = (d & 1) ? cosf(ang) : sinf(ang);
}

// ---------------------------------------------------------------------------
__device__ __forceinline__ uint32_t f2tf32(float x) {
    uint32_t r;
    asm("cvt.rna.tf32.f32 %0, %1;" : "=r"(r) : "f"(x));
    return r;
}
__device__ __forceinline__ float tfr(float x) { return __uint_as_float(f2tf32(x)); }

__device__ __forceinline__ void mma8(float* c, const uint32_t* a, const uint32_t* b) {
    asm volatile(
        "mma.sync.aligned.m16n8k8.row.col.f32.tf32.tf32.f32 "
        "{%0,%1,%2,%3},{%4,%5,%6,%7},{%8,%9},{%0,%1,%2,%3};"
        : "+f"(c[0]), "+f"(c[1]), "+f"(c[2]), "+f"(c[3])
        : "r"(a[0]), "r"(a[1]), "r"(a[2]), "r"(a[3]), "r"(b[0]), "r"(b[1]));
}

__device__ __forceinline__ void cpasync16(uint32_t dst, const void* src) {
    asm volatile("cp.async.cg.shared.global [%0], [%1], 16;" :: "r"(dst), "l"(src));
}

// Swizzled smem staging (16-float rows): conflict-free STS.128
__device__ __forceinline__ void stage16(float* s, int r, int c4, float4 v) {
    float4 w = make_float4(tfr(v.x), tfr(v.y), tfr(v.z), tfr(v.w));
    *(float4*)(s + r * 16 + ((c4 ^ ((r >> 1) & 3)) << 2)) = w;
}

// ---------------------------------------------------------------------------
// Shared GEMM mainloop: acc = A[128, :] @ B[128, :]^T over K=1024
// CTA 128x128, KC=16, 256 thr, 8 warps 4(m)x2(n), warp tile 32x64.
// ---------------------------------------------------------------------------
struct GemmCtx {
    float acc[2][8][4];
};

__device__ __forceinline__ void gemm_mainloop(
    const float* __restrict__ A, const float* __restrict__ B,
    int cm, int cn, float (*As)[2048], float (*Bs)[2048], GemmCtx& g)
{
    constexpr int K  = 1024;
    constexpr int KT = K / 16;

    const int tid = threadIdx.x;
    const int arow = tid >> 2;
    const int ac4  = tid & 3;
    const float* Aptr0 = A + (size_t)(cm + arow)      * K + ac4 * 4;
    const float* Aptr1 = A + (size_t)(cm + arow + 64) * K + ac4 * 4;
    const float* Bptr0 = B + (size_t)(cn + arow)      * K + ac4 * 4;
    const float* Bptr1 = B + (size_t)(cn + arow + 64) * K + ac4 * 4;

    const int wid  = tid >> 5;
    const int lane = tid & 31;
    const int gid  = lane >> 2;
    const int tg   = lane & 3;
    const int wm = (wid & 3) * 32;
    const int wn = (wid >> 2) * 64;

    // swizzle key identical for all fragment rows of this thread
    const int kx4 = ((gid >> 1) & 3) << 2;
    int xoff[4];
#pragma unroll
    for (int j = 0; j < 4; j++) xoff[j] = ((j << 2) ^ kx4) + tg;
    const int baseA = (wm + gid) * 16;
    const int baseB = (wn + gid) * 16;

#pragma unroll
    for (int i = 0; i < 2; i++)
#pragma unroll
        for (int j = 0; j < 8; j++)
#pragma unroll
            for (int l = 0; l < 4; l++) g.acc[i][j][l] = 0.f;

    stage16(As[0], arow,      ac4, *(const float4*)Aptr0);
    stage16(As[0], arow + 64, ac4, *(const float4*)Aptr1);
    stage16(Bs[0], arow,      ac4, *(const float4*)Bptr0);
    stage16(Bs[0], arow + 64, ac4, *(const float4*)Bptr1);
    __syncthreads();

    for (int kt = 0; kt < KT; kt++) {
        const int buf = kt & 1;
        float4 ra0, ra1, rb0, rb1;
        const bool pf = (kt + 1 < KT);
        if (pf) {
            ra0 = *(const float4*)(Aptr0 + (kt + 1) * 16);
            ra1 = *(const float4*)(Aptr1 + (kt + 1) * 16);
            rb0 = *(const float4*)(Bptr0 + (kt + 1) * 16);
            rb1 = *(const float4*)(Bptr1 + (kt + 1) * 16);
        }

        const float* as_ = As[buf];
        const float* bs_ = Bs[buf];
#pragma unroll
        for (int kk = 0; kk < 2; kk++) {
            const int xa = xoff[2 * kk];
            const int xb = xoff[2 * kk + 1];
            uint32_t af[2][4], bf[8][2];
#pragma unroll
            for (int im = 0; im < 2; im++) {
                af[im][0] = __float_as_uint(as_[baseA + im * 256 +       xa]);
                af[im][1] = __float_as_uint(as_[baseA + im * 256 + 128 + xa]);
                af[im][2] = __float_as_uint(as_[baseA + im * 256 +       xb]);
                af[im][3] = __float_as_uint(as_[baseA + im * 256 + 128 + xb]);
            }
#pragma unroll
            for (int in_ = 0; in_ < 8; in_++) {
                bf[in_][0] = __float_as_uint(bs_[baseB + in_ * 128 + xa]);
                bf[in_][1] = __float_as_uint(bs_[baseB + in_ * 128 + xb]);
            }
#pragma unroll
            for (int im = 0; im < 2; im++)
#pragma unroll
                for (int in_ = 0; in_ < 8; in_++)
                    mma8(g.acc[im][in_], af[im], bf[in_]);
        }

        if (pf) {
            float* asn = As[buf ^ 1];
            float* bsn = Bs[buf ^ 1];
            stage16(asn, arow,      ac4, ra0);
            stage16(asn, arow + 64, ac4, ra1);
            stage16(bsn, arow,      ac4, rb0);
            stage16(bsn, arow + 64, ac4, rb1);
        }
        __syncthreads();
    }
}

// ---------------------------------------------------------------------------
// Merged Q/K/V projection kernel: blockIdx.z selects the projection.
// ---------------------------------------------------------------------------
__global__ __launch_bounds__(256, 2)
void qkv_kernel(const float* __restrict__ q, const float* __restrict__ k,
                const float* __restrict__ v,
                const float* __restrict__ Wq, const float* __restrict__ Wk,
                const float* __restrict__ Wv,
                const float* __restrict__ bq, const float* __restrict__ bk,
                const float* __restrict__ bv) {
    __shared__ float As[2][2048];
    __shared__ float Bs[2][2048];

    const int z = blockIdx.z;
    const float* A    = (z == 0) ? q  : (z == 1) ? k  : v;
    const float* B    = (z == 0) ? Wq : (z == 1) ? Wk : Wv;
    const float* bias = (z == 0) ? bq : (z == 1) ? bk : bv;

    const int cm = blockIdx.x * 128;
    const int cn = blockIdx.y * 128;

    GemmCtx g;
    gemm_mainloop(A, B, cm, cn, As, Bs, g);

    const int tid = threadIdx.x;
    const int wid = tid >> 5, lane = tid & 31;
    const int gid = lane >> 2, tg = lane & 3;
    const int wm = (wid & 3) * 32, wn = (wid >> 2) * 64;

    float* dstQK = (z == 0) ? g_Qh : g_Kh;

#pragma unroll
    for (int im = 0; im < 2; im++) {
#pragma unroll
        for (int in_ = 0; in_ < 8; in_++) {
#pragma unroll
            for (int e = 0; e < 4; e++) {
                int m = cm + wm + im * 16 + gid + (e >> 1) * 8;
                int n = cn + wn + in_ * 8 + tg * 2 + (e & 1);
                float val = g.acc[im][in_][e];
                int b = m >> 10, s = m & 1023, h = n >> 6, d = n & 63;
                if (z == 2) {
                    val = tfr(val + bias[n]);
                    g_VhT[((size_t)((b * NH + h) * HD + d)) * SEQ + s] = val;
                } else {
                    val = tfr(val + bias[n] + g_PE[(s << 6) + d]);
                    dstQK[((size_t)((b * NH + h) * SEQ + s)) * HD + d] = val;
                }
            }
        }
    }
}

// ---------------------------------------------------------------------------
// Output projection: out = g_AO @ Wo^T + bo
// ---------------------------------------------------------------------------
__global__ __launch_bounds__(256, 2)
void oproj_kernel(const float* __restrict__ Wo, const float* __restrict__ bo,
                  float* __restrict__ out) {
    __shared__ float As[2][2048];
    __shared__ float Bs[2][2048];

    const int cm = blockIdx.x * 128;
    const int cn = blockIdx.y * 128;

    GemmCtx g;
    gemm_mainloop(g_AO, Wo, cm, cn, As, Bs, g);

    const int tid = threadIdx.x;
    const int wid = tid >> 5, lane = tid & 31;
    const int gid = lane >> 2, tg = lane & 3;
    const int wm = (wid & 3) * 32, wn = (wid >> 2) * 64;

#pragma unroll
    for (int im = 0; im < 2; im++) {
#pragma unroll
        for (int in_ = 0; in_ < 8; in_++) {
            int r0 = cm + wm + im * 16 + gid;
            int c0 = cn + wn + in_ * 8 + tg * 2;
            out[(size_t)r0 * DM + c0]           = g.acc[im][in_][0] + bo[c0];
            out[(size_t)r0 * DM + c0 + 1]       = g.acc[im][in_][1] + bo[c0 + 1];
            out[(size_t)(r0 + 8) * DM + c0]     = g.acc[im][in_][2] + bo[c0];
            out[(size_t)(r0 + 8) * DM + c0 + 1] = g.acc[im][in_][3] + bo[c0 + 1];
        }
    }
}

// ---------------------------------------------------------------------------
// Flash attention. Block = (128 q-rows, bh). 256 thr, warp owns 16 q-rows.
// P never touches smem: QK C-fragment reused as PV A-fragment; the column
// permutation is absorbed into K/V (LDS.64 at cols 2tg,2tg+1) and Q loads.
// K/V staged by cp.async into swizzled stride-80 tiles, double-buffered.
// smem: 2x5120 (K) + 2x5120 (V) floats = 80KB.
// ---------------------------------------------------------------------------
#define KVS 80
#define FLASH_SMEM_BYTES (20480 * 4)

__global__ __launch_bounds__(256, 2)
void flash_kernel() {
    extern __shared__ float sm[];
    float* KsB = sm;                 // 2 x 5120
    float* VsB = sm + 10240;         // 2 x 5120

    const int tid  = threadIdx.x;
    const int lane = tid & 31;
    const int w    = tid >> 5;
    const int gid  = lane >> 2;
    const int tg   = lane & 3;
    const int qt   = blockIdx.x;
    const int bh   = blockIdx.y;

    const float* Qb = g_Qh  + (size_t)bh * (SEQ * HD);
    const float* Kb = g_Kh  + (size_t)bh * (SEQ * HD);
    const float* Vb = g_VhT + (size_t)bh * (HD * SEQ);

    // Q fragments with permuted k-cols: qf[kk] holds Q[g][8kk+2tg..+1], rows g,g+8
    uint32_t qf[8][4];
    {
        const float* q0 = Qb + (size_t)(qt * 128 + w * 16 + gid) * HD + 2 * tg;
        const float* q1 = q0 + 8 * HD;
#pragma unroll
        for (int kk = 0; kk < 8; kk++) {
            float2 a = *(const float2*)(q0 + kk * 8);
            float2 b = *(const float2*)(q1 + kk * 8);
            qf[kk][0] = __float_as_uint(a.x);
            qf[kk][1] = __float_as_uint(b.x);
            qf[kk][2] = __float_as_uint(a.y);
            qf[kk][3] = __float_as_uint(b.y);
        }
    }

    // cp.async staging: thread (ln=tid>>2 row, q4=tid&3 16-col group)
    const int ln = tid >> 2;
    const int q4 = tid & 3;
    const int sw = (ln >> 1) & 3;
    const uint32_t ksm = (uint32_t)__cvta_generic_to_shared(KsB) + ln * (KVS * 4);
    const uint32_t vsm = (uint32_t)__cvta_generic_to_shared(VsB) + ln * (KVS * 4);
    uint32_t co[4];
#pragma unroll
    for (int i = 0; i < 4; i++) co[i] = (uint32_t)(((q4 * 4 + i) ^ sw) << 4);
    const float* kg = Kb + (size_t)ln * HD + q4 * 16;
    const float* vg = Vb + (size_t)ln * SEQ + q4 * 16;

    // prologue: stage tile 0 into buf 0
#pragma unroll
    for (int i = 0; i < 4; i++) {
        cpasync16(ksm + co[i], kg + i * 4);
        cpasync16(vsm + co[i], vg + i * 4);
    }
    asm volatile("cp.async.commit_group;");
    asm volatile("cp.async.wait_group 0;");
    __syncthreads();

    float m0 = -1e30f, m1 = -1e30f, l0 = 0.f, l1 = 0.f;
    float ao[8][4];
#pragma unroll
    for (int t = 0; t < 8; t++)
#pragma unroll
        for (int j = 0; j < 4; j++) ao[t][j] = 0.f;

    const int th  = tg >> 1;
    const int to  = 2 * (tg & 1);
    const int kxv = (gid >> 1) & 3;
    const int rbase = gid * KVS;

    for (int kt = 0; kt < 16; kt++) {
        const int buf = kt & 1;
        if (kt < 15) {
            const float* kgn = kg + (size_t)(kt + 1) * 64 * HD;
            const float* vgn = vg + (kt + 1) * 64;
            const uint32_t kd = ksm + (uint32_t)((buf ^ 1) * 20480);
            const uint32_t vd = vsm + (uint32_t)((buf ^ 1) * 20480);
#pragma unroll
            for (int i = 0; i < 4; i++) {
                cpasync16(kd + co[i], kgn + i * 4);
                cpasync16(vd + co[i], vgn + i * 4);
            }
            asm volatile("cp.async.commit_group;");
        }

        const float* ks = KsB + buf * 5120;
        const float* vs = VsB + buf * 5120;

        // S = Q @ K^T
        float s[8][4];
#pragma unroll
        for (int t = 0; t < 8; t++)
#pragma unroll
            for (int j = 0; j < 4; j++) s[t][j] = 0.f;

#pragma unroll
        for (int kk = 0; kk < 8; kk++) {
            const int coff = ((((2 * kk + th) ^ kxv)) << 2) + to;
#pragma unroll
            for (int tn = 0; tn < 8; tn++) {
                float2 b = *(const float2*)(ks + tn * (8 * KVS) + rbase + coff);
                uint32_t bb[2] = { __float_as_uint(b.x), __float_as_uint(b.y) };
                mma8(s[tn], qf[kk], bb);
            }
        }

        // scale + row max
        float t0 = -1e30f, t1 = -1e30f;
#pragma unroll
        for (int tn = 0; tn < 8; tn++) {
            s[tn][0] *= 0.125f; s[tn][1] *= 0.125f;
            s[tn][2] *= 0.125f; s[tn][3] *= 0.125f;
            t0 = fmaxf(t0, fmaxf(s[tn][0], s[tn][1]));
            t1 = fmaxf(t1, fmaxf(s[tn][2], s[tn][3]));
        }
        t0 = fmaxf(t0, __shfl_xor_sync(0xffffffffu, t0, 1));
        t0 = fmaxf(t0, __shfl_xor_sync(0xffffffffu, t0, 2));
        t1 = fmaxf(t1, __shfl_xor_sync(0xffffffffu, t1, 1));
        t1 = fmaxf(t1, __shfl_xor_sync(0xffffffffu, t1, 2));

        float mn0 = fmaxf(m0, t0), mn1 = fmaxf(m1, t1);
        float a0 = __expf(m0 - mn0), a1 = __expf(m1 - mn1);

        float rs0 = 0.f, rs1 = 0.f;
#pragma unroll
        for (int tn = 0; tn < 8; tn++) {
            s[tn][0] = __expf(s[tn][0] - mn0);
            s[tn][1] = __expf(s[tn][1] - mn0);
            s[tn][2] = __expf(s[tn][2] - mn1);
            s[tn][3] = __expf(s[tn][3] - mn1);
            rs0 += s[tn][0] + s[tn][1];
            rs1 += s[tn][2] + s[tn][3];
        }
        rs0 += __shfl_xor_sync(0xffffffffu, rs0, 1);
        rs0 += __shfl_xor_sync(0xffffffffu, rs0, 2);
        rs1 += __shfl_xor_sync(0xffffffffu, rs1, 1);
        rs1 += __shfl_xor_sync(0xffffffffu, rs1, 2);

        l0 = l0 * a0 + rs0;
        l1 = l1 * a1 + rs1;
        m0 = mn0; m1 = mn1;
#pragma unroll
        for (int tn = 0; tn < 8; tn++) {
            ao[tn][0] *= a0; ao[tn][1] *= a0;
            ao[tn][2] *= a1; ao[tn][3] *= a1;
        }

        // O += P @ V  (C-fragment of S reused as A-fragment; same permuted-k V loads)
#pragma unroll
        for (int kc = 0; kc < 8; kc++) {
            uint32_t pa[4] = { f2tf32(s[kc][0]), f2tf32(s[kc][2]),
                               f2tf32(s[kc][1]), f2tf32(s[kc][3]) };
            const int coff = ((((2 * kc + th) ^ kxv)) << 2) + to;
#pragma unroll
            for (int tn = 0; tn < 8; tn++) {
                float2 b = *(const float2*)(vs + tn * (8 * KVS) + rbase + coff);
                uint32_t bb[2] = { __float_as_uint(b.x), __float_as_uint(b.y) };
                mma8(ao[tn], pa, bb);
            }
        }

        asm volatile("cp.async.wait_group 0;");
        __syncthreads();
    }

    // normalize + store to g_AO [B,S,D]
    float i0 = 1.f / l0, i1 = 1.f / l1;
    int b = bh >> 4, h = bh & 15;
    size_t srow = (size_t)qt * 128 + w * 16 + gid;
    float* O0 = g_AO + ((size_t)b * SEQ + srow) * DM + h * HD + tg * 2;
    float* O1 = O0 + (size_t)8 * DM;
#pragma unroll
    for (int tn = 0; tn < 8; tn++) {
        *(float2*)(O0 + tn * 8) = make_float2(ao[tn][0] * i0, ao[tn][1] * i0);
        *(float2*)(O1 + tn * 8) = make_float2(ao[tn][2] * i1, ao[tn][3] * i1);
    }
}

// ---------------------------------------------------------------------------
extern "C" void kernel_launch(void* const* d_in, const int* in_sizes, int n_in,
                              void* d_out, int out_size) {
    const float* q  = (const float*)d_in[0];
    const float* k  = (const float*)d_in[1];
    const float* v  = (const float*)d_in[2];
    const float* Wq = (const float*)d_in[3];
    const float* bq = (const float*)d_in[4];
    const float* Wk = (const float*)d_in[5];
    const float* bk = (const float*)d_in[6];
    const float* Wv = (const float*)d_in[7];
    const float* bv = (const float*)d_in[8];
    const float* Wo = (const float*)d_in[9];
    const float* bo = (const float*)d_in[10];
    float* out = (float*)d_out;

    cudaFuncSetAttribute(flash_kernel, cudaFuncAttributeMaxDynamicSharedMemorySize,
                         FLASH_SMEM_BYTES);

    pe_init_kernel<<<256, 256>>>();

    qkv_kernel<<<dim3(32, 8, 3), 256>>>(q, k, v, Wq, Wk, Wv, bq, bk, bv);
    flash_kernel<<<dim3(8, 64), 256, FLASH_SMEM_BYTES>>>();
    oproj_kernel<<<dim3(32, 8), 256>>>(Wo, bo, out);
}

// round 8
// speedup vs baseline: 1.6945x; 1.6945x over previous
#include <cuda_runtime.h>
#include <math.h>
#include <stdint.h>

#define BATCH 4
#define SEQ   1024
#define DM    1024
#define NH    16
#define HD    64
#define BH    (BATCH*NH)

// Scratch (device globals: allocation-free per harness rules)
__device__ float g_rq [BATCH*SEQ*DM];           // tf32-rounded inputs
__device__ float g_rk [BATCH*SEQ*DM];
__device__ float g_rv [BATCH*SEQ*DM];
__device__ float g_rWq[DM*DM];
__device__ float g_rWk[DM*DM];
__device__ float g_rWv[DM*DM];
__device__ float g_rWo[DM*DM];
__device__ float g_Qh [BATCH*NH*SEQ*HD];        // [B,H,S,hd]  (tf32-rounded)
__device__ float g_Kh [BATCH*NH*SEQ*HD];        // [B,H,S,hd]  (tf32-rounded)
__device__ float g_VhT[BATCH*NH*HD*SEQ];        // [B,H,hd,S]  (tf32-rounded)
__device__ float g_AO [BATCH*SEQ*DM];           // [B,S,D] attn out (tf32-rounded)
__device__ float g_PE [SEQ*HD];                 // sinusoidal PE table

// ---------------------------------------------------------------------------
__device__ __forceinline__ uint32_t f2tf32(float x) {
    uint32_t r;
    asm("cvt.rna.tf32.f32 %0, %1;" : "=r"(r) : "f"(x));
    return r;
}
__device__ __forceinline__ float tfr(float x) { return __uint_as_float(f2tf32(x)); }

__device__ __forceinline__ void mma8(float* c, const uint32_t* a, const uint32_t* b) {
    asm volatile(
        "mma.sync.aligned.m16n8k8.row.col.f32.tf32.tf32.f32 "
        "{%0,%1,%2,%3},{%4,%5,%6,%7},{%8,%9},{%0,%1,%2,%3};"
        : "+f"(c[0]), "+f"(c[1]), "+f"(c[2]), "+f"(c[3])
        : "r"(a[0]), "r"(a[1]), "r"(a[2]), "r"(a[3]), "r"(b[0]), "r"(b[1]));
}

__device__ __forceinline__ void cpasync16(uint32_t dst, const void* src) {
    asm volatile("cp.async.cg.shared.global [%0], [%1], 16;" :: "r"(dst), "l"(src));
}
__device__ __forceinline__ void cp_commit() { asm volatile("cp.async.commit_group;"); }
template<int N>
__device__ __forceinline__ void cp_wait() {
    asm volatile("cp.async.wait_group %0;" :: "n"(N));
}

// ---------------------------------------------------------------------------
// PE table
// ---------------------------------------------------------------------------
__global__ void pe_init_kernel() {
    int idx = blockIdx.x * blockDim.x + threadIdx.x;
    if (idx >= SEQ * HD) return;
    int s = idx >> 6;
    int d = idx & 63;
    int de = d & ~1;
    float div = expf(-(float)de * 0.14391156831212787f);   // ln(10000)/64
    float ang = (float)s * div;
    g_PE[idx] = (d & 1) ? cosf(ang) : sinf(ang);
}

// ---------------------------------------------------------------------------
// Prep: round all GEMM operands to tf32-rna once. grid (4096, 7)
// ---------------------------------------------------------------------------
__global__ void prep_kernel(const float4* __restrict__ q, const float4* __restrict__ k,
                            const float4* __restrict__ v,
                            const float4* __restrict__ wq, const float4* __restrict__ wk,
                            const float4* __restrict__ wv, const float4* __restrict__ wo) {
    int i = blockIdx.x * blockDim.x + threadIdx.x;
    int z = blockIdx.y;
    const float4* src;
    float4* dst;
    int n4;
    switch (z) {
        case 0: src = q;  dst = (float4*)g_rq;  n4 = BATCH*SEQ*DM/4; break;
        case 1: src = k;  dst = (float4*)g_rk;  n4 = BATCH*SEQ*DM/4; break;
        case 2: src = v;  dst = (float4*)g_rv;  n4 = BATCH*SEQ*DM/4; break;
        case 3: src = wq; dst = (float4*)g_rWq; n4 = DM*DM/4; break;
        case 4: src = wk; dst = (float4*)g_rWk; n4 = DM*DM/4; break;
        case 5: src = wv; dst = (float4*)g_rWv; n4 = DM*DM/4; break;
        default:src = wo; dst = (float4*)g_rWo; n4 = DM*DM/4; break;
    }
    if (i >= n4) return;
    float4 a = src[i];
    dst[i] = make_float4(tfr(a.x), tfr(a.y), tfr(a.z), tfr(a.w));
}

// ---------------------------------------------------------------------------
// NT GEMM mainloop: acc = A[128,:] @ B[128,:]^T over K=1024.
// Inputs PRE-ROUNDED tf32 -> cp.async raw staging, 3-stage pipeline.
// CTA 128x128, KC=16, 256 thr, 8 warps 4(m)x2(n), warp tile 32x64.
// Swizzled smem rows of 16 floats: float ofs = r*16 + ((c4 ^ ((r>>1)&3))<<2)+(c&3)
// ---------------------------------------------------------------------------
__device__ __forceinline__ void gemm_mainloop(
    const float* __restrict__ A, const float* __restrict__ B,
    int cm, int cn, float (*As)[2048], float (*Bs)[2048], float acc[2][8][4])
{
    constexpr int K  = 1024;
    constexpr int KT = K / 16;

    const int tid  = threadIdx.x;
    const int arow = tid >> 2;          // 0..63
    const int ac4  = tid & 3;
    const uint32_t co = (uint32_t)((ac4 ^ ((arow >> 1) & 3)) << 4);  // byte ofs in row

    const float* pA0 = A + (size_t)(cm + arow)      * K + ac4 * 4;
    const float* pA1 = A + (size_t)(cm + arow + 64) * K + ac4 * 4;
    const float* pB0 = B + (size_t)(cn + arow)      * K + ac4 * 4;
    const float* pB1 = B + (size_t)(cn + arow + 64) * K + ac4 * 4;

    const uint32_t sA = (uint32_t)__cvta_generic_to_shared(As) + arow * 64 + co;
    const uint32_t sB = (uint32_t)__cvta_generic_to_shared(Bs) + arow * 64 + co;

    const int wid  = tid >> 5;
    const int lane = tid & 31;
    const int gid  = lane >> 2;
    const int tg   = lane & 3;
    const int wm = (wid & 3) * 32;
    const int wn = (wid >> 2) * 64;

    const int kx4 = ((gid >> 1) & 3) << 2;
    int xoff[4];
#pragma unroll
    for (int j = 0; j < 4; j++) xoff[j] = ((j << 2) ^ kx4) + tg;
    const int baseA = (wm + gid) * 16;
    const int baseB = (wn + gid) * 16;

#pragma unroll
    for (int i = 0; i < 2; i++)
#pragma unroll
        for (int j = 0; j < 8; j++)
#pragma unroll
            for (int l = 0; l < 4; l++) acc[i][j][l] = 0.f;

    // prologue: stages 0,1
#pragma unroll
    for (int s = 0; s < 2; s++) {
        const uint32_t so = (uint32_t)(s * 8192);
        cpasync16(sA + so,        pA0 + s * 16);
        cpasync16(sA + so + 4096, pA1 + s * 16);
        cpasync16(sB + so,        pB0 + s * 16);
        cpasync16(sB + so + 4096, pB1 + s * 16);
        cp_commit();
    }

    int stage = 0;
    for (int kt = 0; kt < KT; kt++) {
        if (kt + 2 < KT) cp_wait<1>(); else cp_wait<0>();
        __syncthreads();

        if (kt + 2 < KT) {
            int ns = stage + 2; if (ns >= 3) ns -= 3;
            const uint32_t so = (uint32_t)(ns * 8192);
            cpasync16(sA + so,        pA0 + (kt + 2) * 16);
            cpasync16(sA + so + 4096, pA1 + (kt + 2) * 16);
            cpasync16(sB + so,        pB0 + (kt + 2) * 16);
            cpasync16(sB + so + 4096, pB1 + (kt + 2) * 16);
            cp_commit();
        }

        const float* as_ = As[stage];
        const float* bs_ = Bs[stage];
#pragma unroll
        for (int kk = 0; kk < 2; kk++) {
            const int xa = xoff[2 * kk];
            const int xb = xoff[2 * kk + 1];
            uint32_t af[2][4], bf[8][2];
#pragma unroll
            for (int im = 0; im < 2; im++) {
                af[im][0] = __float_as_uint(as_[baseA + im * 256 +       xa]);
                af[im][1] = __float_as_uint(as_[baseA + im * 256 + 128 + xa]);
                af[im][2] = __float_as_uint(as_[baseA + im * 256 +       xb]);
                af[im][3] = __float_as_uint(as_[baseA + im * 256 + 128 + xb]);
            }
#pragma unroll
            for (int in_ = 0; in_ < 8; in_++) {
                bf[in_][0] = __float_as_uint(bs_[baseB + in_ * 128 + xa]);
                bf[in_][1] = __float_as_uint(bs_[baseB + in_ * 128 + xb]);
            }
#pragma unroll
            for (int im = 0; im < 2; im++)
#pragma unroll
                for (int in_ = 0; in_ < 8; in_++)
                    mma8(acc[im][in_], af[im], bf[in_]);
        }
        __syncthreads();
        if (++stage == 3) stage = 0;
    }
}

// ---------------------------------------------------------------------------
// Merged Q/K/V projection kernel: blockIdx.z selects the projection.
// ---------------------------------------------------------------------------
__global__ __launch_bounds__(256, 2)
void qkv_kernel() {
    __shared__ float As[3][2048];
    __shared__ float Bs[3][2048];

    const int z = blockIdx.z;
    const float* A    = (z == 0) ? g_rq  : (z == 1) ? g_rk  : g_rv;
    const float* B    = (z == 0) ? g_rWq : (z == 1) ? g_rWk : g_rWv;

    const int cm = blockIdx.x * 128;
    const int cn = blockIdx.y * 128;

    float acc[2][8][4];
    gemm_mainloop(A, B, cm, cn, As, Bs, acc);

    const int tid = threadIdx.x;
    const int wid = tid >> 5, lane = tid & 31;
    const int gid = lane >> 2, tg = lane & 3;
    const int wm = (wid & 3) * 32, wn = (wid >> 2) * 64;

    // bias is raw fp32 (from kernel params via constant globals is not available;
    // read through global pointers passed in c_bias) — use __grid_constant__-free path:
    // biases were stashed in g_bias by launch (see kernel_launch).
    extern __device__ float g_bias[];  // fwd decl trick not allowed; use real global below
}

// real biases live here (copied via cudaMemcpyAsync DtoD in kernel_launch is not
// possible for host pointers; instead biases are passed as kernel args)
__global__ __launch_bounds__(256, 2)
void qkv_kernel2(const float* __restrict__ bq, const float* __restrict__ bk,
                 const float* __restrict__ bv) {
    __shared__ float As[3][2048];
    __shared__ float Bs[3][2048];

    const int z = blockIdx.z;
    const float* A    = (z == 0) ? g_rq  : (z == 1) ? g_rk  : g_rv;
    const float* B    = (z == 0) ? g_rWq : (z == 1) ? g_rWk : g_rWv;
    const float* bias = (z == 0) ? bq    : (z == 1) ? bk    : bv;

    const int cm = blockIdx.x * 128;
    const int cn = blockIdx.y * 128;

    float acc[2][8][4];
    gemm_mainloop(A, B, cm, cn, As, Bs, acc);

    const int tid = threadIdx.x;
    const int wid = tid >> 5, lane = tid & 31;
    const int gid = lane >> 2, tg = lane & 3;
    const int wm = (wid & 3) * 32, wn = (wid >> 2) * 64;

    float* dstQK = (z == 0) ? g_Qh : g_Kh;

#pragma unroll
    for (int im = 0; im < 2; im++) {
#pragma unroll
        for (int in_ = 0; in_ < 8; in_++) {
#pragma unroll
            for (int e = 0; e < 4; e++) {
                int m = cm + wm + im * 16 + gid + (e >> 1) * 8;
                int n = cn + wn + in_ * 8 + tg * 2 + (e & 1);
                float val = acc[im][in_][e];
                int b = m >> 10, s = m & 1023, h = n >> 6, d = n & 63;
                if (z == 2) {
                    val = tfr(val + bias[n]);
                    g_VhT[((size_t)((b * NH + h) * HD + d)) * SEQ + s] = val;
                } else {
                    val = tfr(val + bias[n] + g_PE[(s << 6) + d]);
                    dstQK[((size_t)((b * NH + h) * SEQ + s)) * HD + d] = val;
                }
            }
        }
    }
}

// ---------------------------------------------------------------------------
// Output projection: out = g_AO @ g_rWo^T + bo
// ---------------------------------------------------------------------------
__global__ __launch_bounds__(256, 2)
void oproj_kernel(const float* __restrict__ bo, float* __restrict__ out) {
    __shared__ float As[3][2048];
    __shared__ float Bs[3][2048];

    const int cm = blockIdx.x * 128;
    const int cn = blockIdx.y * 128;

    float acc[2][8][4];
    gemm_mainloop(g_AO, g_rWo, cm, cn, As, Bs, acc);

    const int tid = threadIdx.x;
    const int wid = tid >> 5, lane = tid & 31;
    const int gid = lane >> 2, tg = lane & 3;
    const int wm = (wid & 3) * 32, wn = (wid >> 2) * 64;

#pragma unroll
    for (int im = 0; im < 2; im++) {
#pragma unroll
        for (int in_ = 0; in_ < 8; in_++) {
            int r0 = cm + wm + im * 16 + gid;
            int c0 = cn + wn + in_ * 8 + tg * 2;
            out[(size_t)r0 * DM + c0]           = acc[im][in_][0] + bo[c0];
            out[(size_t)r0 * DM + c0 + 1]       = acc[im][in_][1] + bo[c0 + 1];
            out[(size_t)(r0 + 8) * DM + c0]     = acc[im][in_][2] + bo[c0];
            out[(size_t)(r0 + 8) * DM + c0 + 1] = acc[im][in_][3] + bo[c0 + 1];
        }
    }
}

// ---------------------------------------------------------------------------
// Flash attention. Block = (128 q-rows, bh). 256 thr, warp owns 16 q-rows.
// P never touches smem: QK C-fragment reused as PV A-fragment; the column
// permutation is absorbed into K/V (LDS.64 at cols 2tg,2tg+1) and Q loads.
// K/V staged by cp.async into swizzled stride-80 tiles, double-buffered.
// ---------------------------------------------------------------------------
#define KVS 80
#define FLASH_SMEM_BYTES (20480 * 4)

__global__ __launch_bounds__(256, 2)
void flash_kernel() {
    extern __shared__ float sm[];
    float* KsB = sm;                 // 2 x 5120
    float* VsB = sm + 10240;         // 2 x 5120

    const int tid  = threadIdx.x;
    const int lane = tid & 31;
    const int w    = tid >> 5;
    const int gid  = lane >> 2;
    const int tg   = lane & 3;
    const int qt   = blockIdx.x;
    const int bh   = blockIdx.y;

    const float* Qb = g_Qh  + (size_t)bh * (SEQ * HD);
    const float* Kb = g_Kh  + (size_t)bh * (SEQ * HD);
    const float* Vb = g_VhT + (size_t)bh * (HD * SEQ);

    // Q fragments with permuted k-cols: qf[kk] holds Q[g][8kk+2tg..+1], rows g,g+8
    uint32_t qf[8][4];
    {
        const float* q0 = Qb + (size_t)(qt * 128 + w * 16 + gid) * HD + 2 * tg;
        const float* q1 = q0 + 8 * HD;
#pragma unroll
        for (int kk = 0; kk < 8; kk++) {
            float2 a = *(const float2*)(q0 + kk * 8);
            float2 b = *(const float2*)(q1 + kk * 8);
            qf[kk][0] = __float_as_uint(a.x);
            qf[kk][1] = __float_as_uint(b.x);
            qf[kk][2] = __float_as_uint(a.y);
            qf[kk][3] = __float_as_uint(b.y);
        }
    }

    // cp.async staging: thread (ln=tid>>2 row, q4=tid&3 16-col group)
    const int ln = tid >> 2;
    const int q4 = tid & 3;
    const int sw = (ln >> 1) & 3;
    const uint32_t ksm = (uint32_t)__cvta_generic_to_shared(KsB) + ln * (KVS * 4);
    const uint32_t vsm = (uint32_t)__cvta_generic_to_shared(VsB) + ln * (KVS * 4);
    uint32_t co[4];
#pragma unroll
    for (int i = 0; i < 4; i++) co[i] = (uint32_t)(((q4 * 4 + i) ^ sw) << 4);
    const float* kg = Kb + (size_t)ln * HD + q4 * 16;
    const float* vg = Vb + (size_t)ln * SEQ + q4 * 16;

    // prologue: stage tile 0 into buf 0
#pragma unroll
    for (int i = 0; i < 4; i++) {
        cpasync16(ksm + co[i], kg + i * 4);
        cpasync16(vsm + co[i], vg + i * 4);
    }
    cp_commit();
    cp_wait<0>();
    __syncthreads();

    float m0 = -1e30f, m1 = -1e30f, l0 = 0.f, l1 = 0.f;
    float ao[8][4];
#pragma unroll
    for (int t = 0; t < 8; t++)
#pragma unroll
        for (int j = 0; j < 4; j++) ao[t][j] = 0.f;

    const int th  = tg >> 1;
    const int to  = 2 * (tg & 1);
    const int kxv = (gid >> 1) & 3;
    const int rbase = gid * KVS;

    for (int kt = 0; kt < 16; kt++) {
        const int buf = kt & 1;
        if (kt < 15) {
            const float* kgn = kg + (size_t)(kt + 1) * 64 * HD;
            const float* vgn = vg + (kt + 1) * 64;
            const uint32_t kd = ksm + (uint32_t)((buf ^ 1) * 20480);
            const uint32_t vd = vsm + (uint32_t)((buf ^ 1) * 20480);
#pragma unroll
            for (int i = 0; i < 4; i++) {
                cpasync16(kd + co[i], kgn + i * 4);
                cpasync16(vd + co[i], vgn + i * 4);
            }
            cp_commit();
        }

        const float* ks = KsB + buf * 5120;
        const float* vs = VsB + buf * 5120;

        // S = Q @ K^T
        float s[8][4];
#pragma unroll
        for (int t = 0; t < 8; t++)
#pragma unroll
            for (int j = 0; j < 4; j++) s[t][j] = 0.f;

#pragma unroll
        for (int kk = 0; kk < 8; kk++) {
            const int coff = ((((2 * kk + th) ^ kxv)) << 2) + to;
#pragma unroll
            for (int tn = 0; tn < 8; tn++) {
                float2 b = *(const float2*)(ks + tn * (8 * KVS) + rbase + coff);
                uint32_t bb[2] = { __float_as_uint(b.x), __float_as_uint(b.y) };
                mma8(s[tn], qf[kk], bb);
            }
        }

        // scale + row max
        float t0 = -1e30f, t1 = -1e30f;
#pragma unroll
        for (int tn = 0; tn < 8; tn++) {
            s[tn][0] *= 0.125f; s[tn][1] *= 0.125f;
            s[tn][2] *= 0.125f; s[tn][3] *= 0.125f;
            t0 = fmaxf(t0, fmaxf(s[tn][0], s[tn][1]));
            t1 = fmaxf(t1, fmaxf(s[tn][2], s[tn][3]));
        }
        t0 = fmaxf(t0, __shfl_xor_sync(0xffffffffu, t0, 1));
        t0 = fmaxf(t0, __shfl_xor_sync(0xffffffffu, t0, 2));
        t1 = fmaxf(t1, __shfl_xor_sync(0xffffffffu, t1, 1));
        t1 = fmaxf(t1, __shfl_xor_sync(0xffffffffu, t1, 2));

        float mn0 = fmaxf(m0, t0), mn1 = fmaxf(m1, t1);
        float a0 = __expf(m0 - mn0), a1 = __expf(m1 - mn1);

        float rs0 = 0.f, rs1 = 0.f;
#pragma unroll
        for (int tn = 0; tn < 8; tn++) {
            s[tn][0] = __expf(s[tn][0] - mn0);
            s[tn][1] = __expf(s[tn][1] - mn0);
            s[tn][2] = __expf(s[tn][2] - mn1);
            s[tn][3] = __expf(s[tn][3] - mn1);
            rs0 += s[tn][0] + s[tn][1];
            rs1 += s[tn][2] + s[tn][3];
        }
        rs0 += __shfl_xor_sync(0xffffffffu, rs0, 1);
        rs0 += __shfl_xor_sync(0xffffffffu, rs0, 2);
        rs1 += __shfl_xor_sync(0xffffffffu, rs1, 1);
        rs1 += __shfl_xor_sync(0xffffffffu, rs1, 2);

        l0 = l0 * a0 + rs0;
        l1 = l1 * a1 + rs1;
        m0 = mn0; m1 = mn1;
#pragma unroll
        for (int tn = 0; tn < 8; tn++) {
            ao[tn][0] *= a0; ao[tn][1] *= a0;
            ao[tn][2] *= a1; ao[tn][3] *= a1;
        }

        // O += P @ V  (C-fragment of S reused as A-fragment; same permuted-k V loads)
#pragma unroll
        for (int kc = 0; kc < 8; kc++) {
            uint32_t pa[4] = { f2tf32(s[kc][0]), f2tf32(s[kc][2]),
                               f2tf32(s[kc][1]), f2tf32(s[kc][3]) };
            const int coff = ((((2 * kc + th) ^ kxv)) << 2) + to;
#pragma unroll
            for (int tn = 0; tn < 8; tn++) {
                float2 b = *(const float2*)(vs + tn * (8 * KVS) + rbase + coff);
                uint32_t bb[2] = { __float_as_uint(b.x), __float_as_uint(b.y) };
                mma8(ao[tn], pa, bb);
            }
        }

        cp_wait<0>();
        __syncthreads();
    }

    // normalize + tf32-round + store to g_AO [B,S,D] (oproj consumes raw)
    float i0 = 1.f / l0, i1 = 1.f / l1;
    int b = bh >> 4, h = bh & 15;
    size_t srow = (size_t)qt * 128 + w * 16 + gid;
    float* O0 = g_AO + ((size_t)b * SEQ + srow) * DM + h * HD + tg * 2;
    float* O1 = O0 + (size_t)8 * DM;
#pragma unroll
    for (int tn = 0; tn < 8; tn++) {
        *(float2*)(O0 + tn * 8) = make_float2(tfr(ao[tn][0] * i0), tfr(ao[tn][1] * i0));
        *(float2*)(O1 + tn * 8) = make_float2(tfr(ao[tn][2] * i1), tfr(ao[tn][3] * i1));
    }
}

// ---------------------------------------------------------------------------
extern "C" void kernel_launch(void* const* d_in, const int* in_sizes, int n_in,
                              void* d_out, int out_size) {
    const float* q  = (const float*)d_in[0];
    const float* k  = (const float*)d_in[1];
    const float* v  = (const float*)d_in[2];
    const float* Wq = (const float*)d_in[3];
    const float* bq = (const float*)d_in[4];
    const float* Wk = (const float*)d_in[5];
    const float* bk = (const float*)d_in[6];
    const float* Wv = (const float*)d_in[7];
    const float* bv = (const float*)d_in[8];
    const float* Wo = (const float*)d_in[9];
    const float* bo = (const float*)d_in[10];
    float* out = (float*)d_out;

    cudaFuncSetAttribute(flash_kernel, cudaFuncAttributeMaxDynamicSharedMemorySize,
                         FLASH_SMEM_BYTES);

    pe_init_kernel<<<256, 256>>>();
    prep_kernel<<<dim3(4096, 7), 256>>>((const float4*)q, (const float4*)k,
                                        (const float4*)v, (const float4*)Wq,
                                        (const float4*)Wk, (const float4*)Wv,
                                        (const float4*)Wo);

    qkv_kernel2<<<dim3(32, 8, 3), 256>>>(bq, bk, bv);
    flash_kernel<<<dim3(8, 64), 256, FLASH_SMEM_BYTES>>>();
    oproj_kernel<<<dim3(32, 8), 256>>>(bo, out);
}

// round 9
// speedup vs baseline: 1.8693x; 1.1032x over previous
#include <cuda_runtime.h>
#include <math.h>
#include <stdint.h>

#define BATCH 4
#define SEQ   1024
#define DM    1024
#define NH    16
#define HD    64
#define BH    (BATCH*NH)

// Scratch (device globals: allocation-free per harness rules)
__device__ float g_rq [BATCH*SEQ*DM];           // tf32-rounded inputs
__device__ float g_rk [BATCH*SEQ*DM];
__device__ float g_rv [BATCH*SEQ*DM];
__device__ float g_rWq[DM*DM];
__device__ float g_rWk[DM*DM];
__device__ float g_rWv[DM*DM];
__device__ float g_rWo[DM*DM];
__device__ float g_Qh [BATCH*NH*SEQ*HD];        // [B,H,S,hd]  (tf32-rounded)
__device__ float g_Kh [BATCH*NH*SEQ*HD];        // [B,H,S,hd]  (tf32-rounded)
__device__ float g_VhT[BATCH*NH*HD*SEQ];        // [B,H,hd,S]  (tf32-rounded)
__device__ float g_AO [BATCH*SEQ*DM];           // [B,S,D] attn out (tf32-rounded)
__device__ float g_PE [SEQ*HD];                 // sinusoidal PE table

// ---------------------------------------------------------------------------
__device__ __forceinline__ uint32_t f2tf32(float x) {
    uint32_t r;
    asm("cvt.rna.tf32.f32 %0, %1;" : "=r"(r) : "f"(x));
    return r;
}
__device__ __forceinline__ float tfr(float x) { return __uint_as_float(f2tf32(x)); }

__device__ __forceinline__ void mma8(float* c, const uint32_t* a, const uint32_t* b) {
    asm volatile(
        "mma.sync.aligned.m16n8k8.row.col.f32.tf32.tf32.f32 "
        "{%0,%1,%2,%3},{%4,%5,%6,%7},{%8,%9},{%0,%1,%2,%3};"
        : "+f"(c[0]), "+f"(c[1]), "+f"(c[2]), "+f"(c[3])
        : "r"(a[0]), "r"(a[1]), "r"(a[2]), "r"(a[3]), "r"(b[0]), "r"(b[1]));
}

__device__ __forceinline__ void cpasync16(uint32_t dst, const void* src) {
    asm volatile("cp.async.cg.shared.global [%0], [%1], 16;" :: "r"(dst), "l"(src));
}
__device__ __forceinline__ void cp_commit() { asm volatile("cp.async.commit_group;"); }
template<int N>
__device__ __forceinline__ void cp_wait() {
    asm volatile("cp.async.wait_group %0;" :: "n"(N));
}

// ---------------------------------------------------------------------------
// PE table
// ---------------------------------------------------------------------------
__global__ void pe_init_kernel() {
    int idx = blockIdx.x * blockDim.x + threadIdx.x;
    if (idx >= SEQ * HD) return;
    int s = idx >> 6;
    int d = idx & 63;
    int de = d & ~1;
    float div = expf(-(float)de * 0.14391156831212787f);   // ln(10000)/64
    float ang = (float)s * div;
    g_PE[idx] = (d & 1) ? cosf(ang) : sinf(ang);
}

// ---------------------------------------------------------------------------
// Prep: round all GEMM operands to tf32-rna once. grid (4096, 7)
// ---------------------------------------------------------------------------
__global__ void prep_kernel(const float4* __restrict__ q, const float4* __restrict__ k,
                            const float4* __restrict__ v,
                            const float4* __restrict__ wq, const float4* __restrict__ wk,
                            const float4* __restrict__ wv, const float4* __restrict__ wo) {
    int i = blockIdx.x * blockDim.x + threadIdx.x;
    int z = blockIdx.y;
    const float4* src;
    float4* dst;
    int n4;
    switch (z) {
        case 0: src = q;  dst = (float4*)g_rq;  n4 = BATCH*SEQ*DM/4; break;
        case 1: src = k;  dst = (float4*)g_rk;  n4 = BATCH*SEQ*DM/4; break;
        case 2: src = v;  dst = (float4*)g_rv;  n4 = BATCH*SEQ*DM/4; break;
        case 3: src = wq; dst = (float4*)g_rWq; n4 = DM*DM/4; break;
        case 4: src = wk; dst = (float4*)g_rWk; n4 = DM*DM/4; break;
        case 5: src = wv; dst = (float4*)g_rWv; n4 = DM*DM/4; break;
        default:src = wo; dst = (float4*)g_rWo; n4 = DM*DM/4; break;
    }
    if (i >= n4) return;
    float4 a = src[i];
    dst[i] = make_float4(tfr(a.x), tfr(a.y), tfr(a.z), tfr(a.w));
}

// ---------------------------------------------------------------------------
// NT GEMM mainloop: acc = A[128,:] @ B[128,:]^T over K=1024.
// Inputs PRE-ROUNDED tf32 -> cp.async raw staging, 3-stage pipeline.
// CTA 128x128, KC=16, 256 thr, 8 warps 4(m)x2(n), warp tile 32x64.
// Swizzled smem rows of 16 floats (scalar fragment LDS: conflict-free).
// ---------------------------------------------------------------------------
__device__ __forceinline__ void gemm_mainloop(
    const float* __restrict__ A, const float* __restrict__ B,
    int cm, int cn, float (*As)[2048], float (*Bs)[2048], float acc[2][8][4])
{
    constexpr int K  = 1024;
    constexpr int KT = K / 16;

    const int tid  = threadIdx.x;
    const int arow = tid >> 2;          // 0..63
    const int ac4  = tid & 3;
    const uint32_t co = (uint32_t)((ac4 ^ ((arow >> 1) & 3)) << 4);  // byte ofs in row

    const float* pA0 = A + (size_t)(cm + arow)      * K + ac4 * 4;
    const float* pA1 = A + (size_t)(cm + arow + 64) * K + ac4 * 4;
    const float* pB0 = B + (size_t)(cn + arow)      * K + ac4 * 4;
    const float* pB1 = B + (size_t)(cn + arow + 64) * K + ac4 * 4;

    const uint32_t sA = (uint32_t)__cvta_generic_to_shared(As) + arow * 64 + co;
    const uint32_t sB = (uint32_t)__cvta_generic_to_shared(Bs) + arow * 64 + co;

    const int wid  = tid >> 5;
    const int lane = tid & 31;
    const int gid  = lane >> 2;
    const int tg   = lane & 3;
    const int wm = (wid & 3) * 32;
    const int wn = (wid >> 2) * 64;

    const int kx4 = ((gid >> 1) & 3) << 2;
    int xoff[4];
#pragma unroll
    for (int j = 0; j < 4; j++) xoff[j] = ((j << 2) ^ kx4) + tg;
    const int baseA = (wm + gid) * 16;
    const int baseB = (wn + gid) * 16;

#pragma unroll
    for (int i = 0; i < 2; i++)
#pragma unroll
        for (int j = 0; j < 8; j++)
#pragma unroll
            for (int l = 0; l < 4; l++) acc[i][j][l] = 0.f;

    // prologue: stages 0,1
#pragma unroll
    for (int s = 0; s < 2; s++) {
        const uint32_t so = (uint32_t)(s * 8192);
        cpasync16(sA + so,        pA0 + s * 16);
        cpasync16(sA + so + 4096, pA1 + s * 16);
        cpasync16(sB + so,        pB0 + s * 16);
        cpasync16(sB + so + 4096, pB1 + s * 16);
        cp_commit();
    }

    int stage = 0;
    for (int kt = 0; kt < KT; kt++) {
        if (kt + 2 < KT) cp_wait<1>(); else cp_wait<0>();
        __syncthreads();

        if (kt + 2 < KT) {
            int ns = stage + 2; if (ns >= 3) ns -= 3;
            const uint32_t so = (uint32_t)(ns * 8192);
            cpasync16(sA + so,        pA0 + (kt + 2) * 16);
            cpasync16(sA + so + 4096, pA1 + (kt + 2) * 16);
            cpasync16(sB + so,        pB0 + (kt + 2) * 16);
            cpasync16(sB + so + 4096, pB1 + (kt + 2) * 16);
            cp_commit();
        }

        const float* as_ = As[stage];
        const float* bs_ = Bs[stage];
#pragma unroll
        for (int kk = 0; kk < 2; kk++) {
            const int xa = xoff[2 * kk];
            const int xb = xoff[2 * kk + 1];
            uint32_t af[2][4], bf[8][2];
#pragma unroll
            for (int im = 0; im < 2; im++) {
                af[im][0] = __float_as_uint(as_[baseA + im * 256 +       xa]);
                af[im][1] = __float_as_uint(as_[baseA + im * 256 + 128 + xa]);
                af[im][2] = __float_as_uint(as_[baseA + im * 256 +       xb]);
                af[im][3] = __float_as_uint(as_[baseA + im * 256 + 128 + xb]);
            }
#pragma unroll
            for (int in_ = 0; in_ < 8; in_++) {
                bf[in_][0] = __float_as_uint(bs_[baseB + in_ * 128 + xa]);
                bf[in_][1] = __float_as_uint(bs_[baseB + in_ * 128 + xb]);
            }
#pragma unroll
            for (int im = 0; im < 2; im++)
#pragma unroll
                for (int in_ = 0; in_ < 8; in_++)
                    mma8(acc[im][in_], af[im], bf[in_]);
        }
        __syncthreads();
        if (++stage == 3) stage = 0;
    }
}

// ---------------------------------------------------------------------------
// Merged Q/K/V projection kernel: blockIdx.z selects the projection.
// ---------------------------------------------------------------------------
__global__ __launch_bounds__(256, 2)
void qkv_kernel2(const float* __restrict__ bq, const float* __restrict__ bk,
                 const float* __restrict__ bv) {
    __shared__ float As[3][2048];
    __shared__ float Bs[3][2048];

    const int z = blockIdx.z;
    const float* A    = (z == 0) ? g_rq  : (z == 1) ? g_rk  : g_rv;
    const float* B    = (z == 0) ? g_rWq : (z == 1) ? g_rWk : g_rWv;
    const float* bias = (z == 0) ? bq    : (z == 1) ? bk    : bv;

    const int cm = blockIdx.x * 128;
    const int cn = blockIdx.y * 128;

    float acc[2][8][4];
    gemm_mainloop(A, B, cm, cn, As, Bs, acc);

    const int tid = threadIdx.x;
    const int wid = tid >> 5, lane = tid & 31;
    const int gid = lane >> 2, tg = lane & 3;
    const int wm = (wid & 3) * 32, wn = (wid >> 2) * 64;

    float* dstQK = (z == 0) ? g_Qh : g_Kh;

#pragma unroll
    for (int im = 0; im < 2; im++) {
#pragma unroll
        for (int in_ = 0; in_ < 8; in_++) {
#pragma unroll
            for (int e = 0; e < 4; e++) {
                int m = cm + wm + im * 16 + gid + (e >> 1) * 8;
                int n = cn + wn + in_ * 8 + tg * 2 + (e & 1);
                float val = acc[im][in_][e];
                int b = m >> 10, s = m & 1023, h = n >> 6, d = n & 63;
                if (z == 2) {
                    val = tfr(val + bias[n]);
                    g_VhT[((size_t)((b * NH + h) * HD + d)) * SEQ + s] = val;
                } else {
                    val = tfr(val + bias[n] + g_PE[(s << 6) + d]);
                    dstQK[((size_t)((b * NH + h) * SEQ + s)) * HD + d] = val;
                }
            }
        }
    }
}

// ---------------------------------------------------------------------------
// Output projection: out = g_AO @ g_rWo^T + bo
// ---------------------------------------------------------------------------
__global__ __launch_bounds__(256, 2)
void oproj_kernel(const float* __restrict__ bo, float* __restrict__ out) {
    __shared__ float As[3][2048];
    __shared__ float Bs[3][2048];

    const int cm = blockIdx.x * 128;
    const int cn = blockIdx.y * 128;

    float acc[2][8][4];
    gemm_mainloop(g_AO, g_rWo, cm, cn, As, Bs, acc);

    const int tid = threadIdx.x;
    const int wid = tid >> 5, lane = tid & 31;
    const int gid = lane >> 2, tg = lane & 3;
    const int wm = (wid & 3) * 32, wn = (wid >> 2) * 64;

#pragma unroll
    for (int im = 0; im < 2; im++) {
#pragma unroll
        for (int in_ = 0; in_ < 8; in_++) {
            int r0 = cm + wm + im * 16 + gid;
            int c0 = cn + wn + in_ * 8 + tg * 2;
            out[(size_t)r0 * DM + c0]           = acc[im][in_][0] + bo[c0];
            out[(size_t)r0 * DM + c0 + 1]       = acc[im][in_][1] + bo[c0 + 1];
            out[(size_t)(r0 + 8) * DM + c0]     = acc[im][in_][2] + bo[c0];
            out[(size_t)(r0 + 8) * DM + c0 + 1] = acc[im][in_][3] + bo[c0 + 1];
        }
    }
}

// ---------------------------------------------------------------------------
// Flash attention. Block = (128 q-rows, bh). 256 thr, warp owns 16 q-rows.
// P never touches smem (QK C-fragment reused as PV A-fragment).
// K/V staged by cp.async into swizzled stride-80 tiles, double-buffered.
// Swizzle key is SHIFTED LEFT 1 bit so it reaches the 8-word block index of
// the float2 fragment reads -> conflict-free LDS.64 (was 2-way conflicted).
// ---------------------------------------------------------------------------
#define KVS 80
#define FLASH_SMEM_BYTES (20480 * 4)

__global__ __launch_bounds__(256, 2)
void flash_kernel() {
    extern __shared__ float sm[];
    float* KsB = sm;                 // 2 x 5120
    float* VsB = sm + 10240;         // 2 x 5120

    const int tid  = threadIdx.x;
    const int lane = tid & 31;
    const int w    = tid >> 5;
    const int gid  = lane >> 2;
    const int tg   = lane & 3;
    const int qt   = blockIdx.x;
    const int bh   = blockIdx.y;

    const float* Qb = g_Qh  + (size_t)bh * (SEQ * HD);
    const float* Kb = g_Kh  + (size_t)bh * (SEQ * HD);
    const float* Vb = g_VhT + (size_t)bh * (HD * SEQ);

    // Q fragments with permuted k-cols: qf[kk] holds Q[g][8kk+2tg..+1], rows g,g+8
    uint32_t qf[8][4];
    {
        const float* q0 = Qb + (size_t)(qt * 128 + w * 16 + gid) * HD + 2 * tg;
        const float* q1 = q0 + 8 * HD;
#pragma unroll
        for (int kk = 0; kk < 8; kk++) {
            float2 a = *(const float2*)(q0 + kk * 8);
            float2 b = *(const float2*)(q1 + kk * 8);
            qf[kk][0] = __float_as_uint(a.x);
            qf[kk][1] = __float_as_uint(b.x);
            qf[kk][2] = __float_as_uint(a.y);
            qf[kk][3] = __float_as_uint(b.y);
        }
    }

    // cp.async staging: thread (ln=tid>>2 row, q4=tid&3 16-col group)
    // swizzle key <<1 so it hits the 8-word block index (conflict-free reads)
    const int ln = tid >> 2;
    const int q4 = tid & 3;
    const int sw = ((ln >> 1) & 3) << 1;
    const uint32_t ksm = (uint32_t)__cvta_generic_to_shared(KsB) + ln * (KVS * 4);
    const uint32_t vsm = (uint32_t)__cvta_generic_to_shared(VsB) + ln * (KVS * 4);
    uint32_t co[4];
#pragma unroll
    for (int i = 0; i < 4; i++) co[i] = (uint32_t)(((q4 * 4 + i) ^ sw) << 4);
    const float* kg = Kb + (size_t)ln * HD + q4 * 16;
    const float* vg = Vb + (size_t)ln * SEQ + q4 * 16;

    // prologue: stage tile 0 into buf 0
#pragma unroll
    for (int i = 0; i < 4; i++) {
        cpasync16(ksm + co[i], kg + i * 4);
        cpasync16(vsm + co[i], vg + i * 4);
    }
    cp_commit();
    cp_wait<0>();
    __syncthreads();

    float m0 = -1e30f, m1 = -1e30f, l0 = 0.f, l1 = 0.f;
    float ao[8][4];
#pragma unroll
    for (int t = 0; t < 8; t++)
#pragma unroll
        for (int j = 0; j < 4; j++) ao[t][j] = 0.f;

    const int th  = tg >> 1;
    const int to  = 2 * (tg & 1);
    const int kxv = ((gid >> 1) & 3) << 1;   // shifted key (matches store side)
    const int rbase = gid * KVS;

    for (int kt = 0; kt < 16; kt++) {
        const int buf = kt & 1;
        if (kt < 15) {
            const float* kgn = kg + (size_t)(kt + 1) * 64 * HD;
            const float* vgn = vg + (kt + 1) * 64;
            const uint32_t kd = ksm + (uint32_t)((buf ^ 1) * 20480);
            const uint32_t vd = vsm + (uint32_t)((buf ^ 1) * 20480);
#pragma unroll
            for (int i = 0; i < 4; i++) {
                cpasync16(kd + co[i], kgn + i * 4);
                cpasync16(vd + co[i], vgn + i * 4);
            }
            cp_commit();
        }

        const float* ks = KsB + buf * 5120;
        const float* vs = VsB + buf * 5120;

        // S = Q @ K^T
        float s[8][4];
#pragma unroll
        for (int t = 0; t < 8; t++)
#pragma unroll
            for (int j = 0; j < 4; j++) s[t][j] = 0.f;

#pragma unroll
        for (int kk = 0; kk < 8; kk++) {
            const int coff = ((((2 * kk + th) ^ kxv)) << 2) + to;
#pragma unroll
            for (int tn = 0; tn < 8; tn++) {
                float2 b = *(const float2*)(ks + tn * (8 * KVS) + rbase + coff);
                uint32_t bb[2] = { __float_as_uint(b.x), __float_as_uint(b.y) };
                mma8(s[tn], qf[kk], bb);
            }
        }

        // scale + row max
        float t0 = -1e30f, t1 = -1e30f;
#pragma unroll
        for (int tn = 0; tn < 8; tn++) {
            s[tn][0] *= 0.125f; s[tn][1] *= 0.125f;
            s[tn][2] *= 0.125f; s[tn][3] *= 0.125f;
            t0 = fmaxf(t0, fmaxf(s[tn][0], s[tn][1]));
            t1 = fmaxf(t1, fmaxf(s[tn][2], s[tn][3]));
        }
        t0 = fmaxf(t0, __shfl_xor_sync(0xffffffffu, t0, 1));
        t0 = fmaxf(t0, __shfl_xor_sync(0xffffffffu, t0, 2));
        t1 = fmaxf(t1, __shfl_xor_sync(0xffffffffu, t1, 1));
        t1 = fmaxf(t1, __shfl_xor_sync(0xffffffffu, t1, 2));

        float mn0 = fmaxf(m0, t0), mn1 = fmaxf(m1, t1);
        float a0 = __expf(m0 - mn0), a1 = __expf(m1 - mn1);

        float rs0 = 0.f, rs1 = 0.f;
#pragma unroll
        for (int tn = 0; tn < 8; tn++) {
            s[tn][0] = __expf(s[tn][0] - mn0);
            s[tn][1] = __expf(s[tn][1] - mn0);
            s[tn][2] = __expf(s[tn][2] - mn1);
            s[tn][3] = __expf(s[tn][3] - mn1);
            rs0 += s[tn][0] + s[tn][1];
            rs1 += s[tn][2] + s[tn][3];
        }
        rs0 += __shfl_xor_sync(0xffffffffu, rs0, 1);
        rs0 += __shfl_xor_sync(0xffffffffu, rs0, 2);
        rs1 += __shfl_xor_sync(0xffffffffu, rs1, 1);
        rs1 += __shfl_xor_sync(0xffffffffu, rs1, 2);

        l0 = l0 * a0 + rs0;
        l1 = l1 * a1 + rs1;
        m0 = mn0; m1 = mn1;
#pragma unroll
        for (int tn = 0; tn < 8; tn++) {
            ao[tn][0] *= a0; ao[tn][1] *= a0;
            ao[tn][2] *= a1; ao[tn][3] *= a1;
        }

        // O += P @ V  (C-fragment of S reused as A-fragment; same permuted-k V loads)
#pragma unroll
        for (int kc = 0; kc < 8; kc++) {
            uint32_t pa[4] = { f2tf32(s[kc][0]), f2tf32(s[kc][2]),
                               f2tf32(s[kc][1]), f2tf32(s[kc][3]) };
            const int coff = ((((2 * kc + th) ^ kxv)) << 2) + to;
#pragma unroll
            for (int tn = 0; tn < 8; tn++) {
                float2 b = *(const float2*)(vs + tn * (8 * KVS) + rbase + coff);
                uint32_t bb[2] = { __float_as_uint(b.x), __float_as_uint(b.y) };
                mma8(ao[tn], pa, bb);
            }
        }

        cp_wait<0>();
        __syncthreads();
    }

    // normalize + tf32-round + store to g_AO [B,S,D] (oproj consumes raw)
    float i0 = 1.f / l0, i1 = 1.f / l1;
    int b = bh >> 4, h = bh & 15;
    size_t srow = (size_t)qt * 128 + w * 16 + gid;
    float* O0 = g_AO + ((size_t)b * SEQ + srow) * DM + h * HD + tg * 2;
    float* O1 = O0 + (size_t)8 * DM;
#pragma unroll
    for (int tn = 0; tn < 8; tn++) {
        *(float2*)(O0 + tn * 8) = make_float2(tfr(ao[tn][0] * i0), tfr(ao[tn][1] * i0));
        *(float2*)(O1 + tn * 8) = make_float2(tfr(ao[tn][2] * i1), tfr(ao[tn][3] * i1));
    }
}

// ---------------------------------------------------------------------------
extern "C" void kernel_launch(void* const* d_in, const int* in_sizes, int n_in,
                              void* d_out, int out_size) {
    const float* q  = (const float*)d_in[0];
    const float* k  = (const float*)d_in[1];
    const float* v  = (const float*)d_in[2];
    const float* Wq = (const float*)d_in[3];
    const float* bq = (const float*)d_in[4];
    const float* Wk = (const float*)d_in[5];
    const float* bk = (const float*)d_in[6];
    const float* Wv = (const float*)d_in[7];
    const float* bv = (const float*)d_in[8];
    const float* Wo = (const float*)d_in[9];
    const float* bo = (const float*)d_in[10];
    float* out = (float*)d_out;

    cudaFuncSetAttribute(flash_kernel, cudaFuncAttributeMaxDynamicSharedMemorySize,
                         FLASH_SMEM_BYTES);

    pe_init_kernel<<<256, 256>>>();
    prep_kernel<<<dim3(4096, 7), 256>>>((const float4*)q, (const float4*)k,
                                        (const float4*)v, (const float4*)Wq,
                                        (const float4*)Wk, (const float4*)Wv,
                                        (const float4*)Wo);

    qkv_kernel2<<<dim3(32, 8, 3), 256>>>(bq, bk, bv);
    flash_kernel<<<dim3(8, 64), 256, FLASH_SMEM_BYTES>>>();
    oproj_kernel<<<dim3(32, 8), 256>>>(bo, out);
}